// round 8
// baseline (speedup 1.0000x reference)
#include <cuda_runtime.h>
#include <cuda_fp16.h>
#include <cstdint>
#include <math_constants.h>

#define NN 100000
#define EE 600000
#define DD 128
#define EPSLN 1e-5f
#define PADH 136   // smem row stride in halves (272B -> conflict-free ldmatrix)

// ---------------- scratch (device globals) -------------------------------------
__device__ float g_y[3L * NN * DD];
__device__ float g_hin[(size_t)NN * DD];
__device__ float g_s0[(size_t)NN * DD];
__device__ float g_s1[(size_t)NN * DD];
__device__ float g_m0[(size_t)NN * DD];
__device__ float g_m1[(size_t)NN * DD];
__device__ float g_slast[(size_t)NN * DD];
__device__ float g_mean[(size_t)NN * DD];
__device__ float g_max[(size_t)NN * DD];
__device__ float g_statsA[9 * 2 * 3 * DD];   // 9 op slots x (sum, sumsq) x 3 x 128
__device__ int   g_deg[NN];
__device__ int   g_rowptr[NN + 1];
__device__ int   g_cursor[NN];
__device__ int   g_ssrc[EE];
__device__ int   g_bsums[256];
__device__ __half g_wpre[27L * 16384];   // per matrix: fp16 W^T [f*128+d]

// ---------------- helpers ------------------------------------------------------
__device__ __forceinline__ uint32_t smem_u32(const void* p) {
    uint32_t a;
    asm("{ .reg .u64 t; cvta.to.shared.u64 t, %1; cvt.u32.u64 %0, t; }" : "=r"(a) : "l"(p));
    return a;
}
__device__ __forceinline__ uint32_t pkh(__half a, __half b) {
    return (uint32_t)__half_as_ushort(a) | ((uint32_t)__half_as_ushort(b) << 16);
}
__device__ __forceinline__ void ldsm_x4(uint32_t& r0, uint32_t& r1, uint32_t& r2, uint32_t& r3,
                                        uint32_t addr) {
    asm volatile("ldmatrix.sync.aligned.m8n8.x4.shared.b16 {%0, %1, %2, %3}, [%4];"
                 : "=r"(r0), "=r"(r1), "=r"(r2), "=r"(r3) : "r"(addr));
}
__device__ __forceinline__ void mma16816h(float* c, const uint32_t* a, const uint32_t* b) {
    asm volatile(
        "mma.sync.aligned.m16n8k16.row.col.f32.f16.f16.f32 "
        "{%0, %1, %2, %3}, {%4, %5, %6, %7}, {%8, %9}, {%0, %1, %2, %3};"
        : "+f"(c[0]), "+f"(c[1]), "+f"(c[2]), "+f"(c[3])
        : "r"(a[0]), "r"(a[1]), "r"(a[2]), "r"(a[3]), "r"(b[0]), "r"(b[1]));
}
__device__ __forceinline__ void cpasync16(uint32_t saddr, const void* gaddr) {
    asm volatile("cp.async.cg.shared.global [%0], [%1], 16;" :: "r"(saddr), "l"(gaddr));
}
__device__ __forceinline__ void cpasync_waitall() {
    asm volatile("cp.async.commit_group;");
    asm volatile("cp.async.wait_group 0;");
}

// ---------------- weight prep: W[d][f] fp32 -> fp16 W^T[f][d] -------------------
__global__ void k_wprep(const float* __restrict__ W, __half* __restrict__ out,
                        float* statszero, int zn) {
    if (statszero && blockIdx.x == 0) {
        for (int i = threadIdx.x; i < zn; i += blockDim.x) statszero[i] = 0.f;
    }
    int m = blockIdx.x >> 3;
    int part = blockIdx.x & 7;
    const float* src = W + (size_t)m * 16384;
    __half* oh = out + (size_t)m * 16384;
    int base = part * 2048;
    for (int i = threadIdx.x; i < 2048; i += blockDim.x) {
        int idx = base + i;
        int d = idx >> 7, f = idx & 127;
        oh[f * 128 + d] = __float2half_rn(src[idx]);
    }
}

// ---------------- fp16 2-pass tensor GEMM + fused column stats ------------------
// y = x @ W^T: A = x split fp16 hi+lo (exact), B = fp16(W) (only error source).
// 256 threads, 8 warps 4x2, warp tile 32x64; full K=128 in ONE chunk; 2 CTAs/SM.
#define TILE_HALVES (128 * PADH)             // 17408 halves = 34816 B
#define SMEM_MMA (3 * TILE_HALVES * 2 + 1024)

__global__ __launch_bounds__(256, 2) void k_gemm_mma(
    const float* __restrict__ x0, const float* __restrict__ x1, const float* __restrict__ x2,
    const __half* __restrict__ wpre, const float* __restrict__ bias,
    float* __restrict__ Y, float* __restrict__ stats, int n, size_t ystride,
    int catmode, int premode)
{
    extern __shared__ char sm[];
    __half* Ahi = (__half*)sm;
    __half* Alo = Ahi + TILE_HALVES;
    __half* Bh  = Alo + TILE_HALVES;
    float* ssum = (float*)(Bh + TILE_HALVES);
    float* ssq  = ssum + 128;

    int tid = threadIdx.x;
    int wid = tid >> 5, lane = tid & 31;
    int wm_ = wid >> 1, wn_ = wid & 1;     // 4x2 warp grid, 32x64 warp tile
    int kcand = catmode ? 0 : blockIdx.z;
    int nchunk = catmode ? 3 : 1;
    int row0 = blockIdx.x * 128;
    float* Yk = Y + (size_t)kcand * ystride;
    const float* bk = bias + kcand * DD;
    int so = kcand * DD;

    if (tid < 128) { ssum[tid] = 0.f; ssq[tid] = 0.f; }

    float c[2][8][4];
    #pragma unroll
    for (int i = 0; i < 2; i++)
        #pragma unroll
        for (int j = 0; j < 8; j++)
            #pragma unroll
            for (int q = 0; q < 4; q++) c[i][j][q] = 0.f;

    int a_row = wm_ * 32 + (lane & 15);
    int a_k8 = (lane >> 4) * 8;
    int b_f = wn_ * 64 + ((lane >> 4) << 3) + (lane & 7);
    int b_k8 = ((lane >> 3) & 1) * 8;
    uint32_t uAhi = smem_u32(Ahi), uAlo = smem_u32(Alo);
    uint32_t uBh = smem_u32(Bh);

    for (int c3 = 0; c3 < nchunk; c3++) {
        const float* X = catmode ? (c3 == 0 ? x0 : (c3 == 1 ? x1 : x2)) : x0;

        if (c3 > 0) __syncthreads();     // prior mma reads done before refill

        // B fill via cp.async: full [128 f][128 k] fp16 tile (one shot)
        {
            int f = tid >> 1, half = tid & 1;
            uint32_t dst = uBh + (uint32_t)(f * PADH * 2) + (uint32_t)(half * 128);
            const char* sh = (const char*)wpre + ((size_t)(catmode ? c3 : kcand) * 16384
                             + (size_t)f * 128 + half * 64) * 2;
            #pragma unroll
            for (int q = 0; q < 8; q++) cpasync16(dst + q * 16, sh + q * 16);
        }
        // A convert fp32 -> fp16 hi/lo (full K=128); optional fused pre-op
        {
            int row = tid >> 1, sg = tid & 1;
            int gr = row0 + row;
            __half* dh = Ahi + row * PADH + sg * 64;
            __half* dl = Alo + row * PADH + sg * 64;
            int cbase = sg * 64;
            #pragma unroll
            for (int q = 0; q < 16; q++) {
                float4 v = make_float4(0.f, 0.f, 0.f, 0.f);
                if (gr < n) {
                    v = *(const float4*)(x0 + (size_t)gr * DD + cbase + q * 4);
                    if (premode && kcand > 0) {
                        float4 b = *(const float4*)(x1 + (size_t)gr * DD + cbase + q * 4);
                        if (kcand == 1) { v.x -= b.x; v.y -= b.y; v.z -= b.z; v.w -= b.w; }
                        else            { v.x *= b.x; v.y *= b.y; v.z *= b.z; v.w *= b.w; }
                    } else if (!premode && !catmode) {
                        if (kcand == 1) v = *(const float4*)(x1 + (size_t)gr * DD + cbase + q * 4);
                        else if (kcand == 2) v = *(const float4*)(x2 + (size_t)gr * DD + cbase + q * 4);
                    } else if (catmode) {
                        v = *(const float4*)(X + (size_t)gr * DD + cbase + q * 4);
                    }
                }
                __half h0 = __float2half_rn(v.x), h1 = __float2half_rn(v.y);
                __half h2 = __float2half_rn(v.z), h3 = __float2half_rn(v.w);
                __half l0 = __float2half_rn(v.x - __half2float(h0));
                __half l1 = __float2half_rn(v.y - __half2float(h1));
                __half l2 = __float2half_rn(v.z - __half2float(h2));
                __half l3 = __float2half_rn(v.w - __half2float(h3));
                *(uint2*)(dh + q * 4) = make_uint2(pkh(h0, h1), pkh(h2, h3));
                *(uint2*)(dl + q * 4) = make_uint2(pkh(l0, l1), pkh(l2, l3));
            }
        }
        cpasync_waitall();
        __syncthreads();

        // 2 fp16 passes per k-step: hi_a*b + lo_a*b (B regs reused)
        #pragma unroll
        for (int k = 0; k < 8; k++) {
            uint32_t ah[2][4], al[2][4];
            #pragma unroll
            for (int mt = 0; mt < 2; mt++) {
                uint32_t off = (uint32_t)(((a_row + mt * 16) * PADH + k * 16 + a_k8) * 2);
                ldsm_x4(ah[mt][0], ah[mt][1], ah[mt][2], ah[mt][3], uAhi + off);
                ldsm_x4(al[mt][0], al[mt][1], al[mt][2], al[mt][3], uAlo + off);
            }
            uint32_t b[4][4];
            #pragma unroll
            for (int p = 0; p < 4; p++) {
                uint32_t addr = uBh + (uint32_t)(((b_f + p * 16) * PADH + k * 16 + b_k8) * 2);
                ldsm_x4(b[p][0], b[p][1], b[p][2], b[p][3], addr);
            }
            #pragma unroll
            for (int mt = 0; mt < 2; mt++)
                #pragma unroll
                for (int nt = 0; nt < 8; nt++) {
                    mma16816h(c[mt][nt], ah[mt], &b[nt >> 1][(nt & 1) * 2]);
                    mma16816h(c[mt][nt], al[mt], &b[nt >> 1][(nt & 1) * 2]);
                }
        }
    }

    // ---------------- epilogue: bias, store Y, fused column stats ---------------
    int erow = lane >> 2, ecp = lane & 3;
    float2 bb[8];
    #pragma unroll
    for (int nt = 0; nt < 8; nt++)
        bb[nt] = *(const float2*)(bk + wn_ * 64 + nt * 8 + ecp * 2);

    float lsum[16], lsq[16];
    #pragma unroll
    for (int j = 0; j < 16; j++) { lsum[j] = 0.f; lsq[j] = 0.f; }

    #pragma unroll
    for (int mt = 0; mt < 2; mt++) {
        int r0g = row0 + wm_ * 32 + mt * 16 + erow;
        int r1g = r0g + 8;
        #pragma unroll
        for (int nt = 0; nt < 8; nt++) {
            int cbase = wn_ * 64 + nt * 8 + ecp * 2;
            float v00 = c[mt][nt][0] + bb[nt].x;
            float v01 = c[mt][nt][1] + bb[nt].y;
            float v10 = c[mt][nt][2] + bb[nt].x;
            float v11 = c[mt][nt][3] + bb[nt].y;
            if (r0g < n) {
                *(float2*)(Yk + (size_t)r0g * DD + cbase) = make_float2(v00, v01);
                lsum[nt * 2]     += v00; lsq[nt * 2]     += v00 * v00;
                lsum[nt * 2 + 1] += v01; lsq[nt * 2 + 1] += v01 * v01;
            }
            if (r1g < n) {
                *(float2*)(Yk + (size_t)r1g * DD + cbase) = make_float2(v10, v11);
                lsum[nt * 2]     += v10; lsq[nt * 2]     += v10 * v10;
                lsum[nt * 2 + 1] += v11; lsq[nt * 2 + 1] += v11 * v11;
            }
        }
    }
    #pragma unroll
    for (int nt = 0; nt < 8; nt++) {
        int cbase = wn_ * 64 + nt * 8 + ecp * 2;
        atomicAdd(&ssum[cbase],     lsum[nt * 2]);
        atomicAdd(&ssq[cbase],      lsq[nt * 2]);
        atomicAdd(&ssum[cbase + 1], lsum[nt * 2 + 1]);
        atomicAdd(&ssq[cbase + 1],  lsq[nt * 2 + 1]);
    }
    __syncthreads();
    if (tid < 128) {
        atomicAdd(&stats[so + tid], ssum[tid]);
        atomicAdd(&stats[3 * DD + so + tid], ssq[tid]);
    }
}

// ---------------- CSR build ---------------------------------------------------
__global__ void k_hist(const int* __restrict__ dst, int* deg, int e) {
    int i = blockIdx.x * blockDim.x + threadIdx.x;
    if (i < e) atomicAdd(&deg[dst[i]], 1);
}
__global__ void k_scan_block(const int* __restrict__ deg, int* incl, int* bsums, int n) {
    __shared__ int sh[1024];
    int i = blockIdx.x * 1024 + threadIdx.x;
    int v = (i < n) ? deg[i] : 0;
    sh[threadIdx.x] = v;
    __syncthreads();
    for (int off = 1; off < 1024; off <<= 1) {
        int t = (threadIdx.x >= off) ? sh[threadIdx.x - off] : 0;
        __syncthreads();
        sh[threadIdx.x] += t;
        __syncthreads();
    }
    if (i < n) incl[i] = sh[threadIdx.x];
    if (threadIdx.x == 1023) bsums[blockIdx.x] = sh[1023];
}
__global__ void k_scan_sums(int* bsums, int nb) {
    if (threadIdx.x == 0 && blockIdx.x == 0) {
        int run = 0;
        for (int i = 0; i < nb; i++) { int t = bsums[i]; bsums[i] = run; run += t; }
    }
}
__global__ void k_scan_fin(const int* __restrict__ deg, const int* __restrict__ incl,
                           const int* __restrict__ bsums, int* rowptr, int* cursor, int n, int e) {
    int i = blockIdx.x * blockDim.x + threadIdx.x;
    if (i < n) {
        int ex = incl[i] - deg[i] + bsums[i >> 10];
        rowptr[i] = ex;
        cursor[i] = ex;
        if (i == n - 1) rowptr[n] = e;
    }
}
__global__ void k_scatter(const int* __restrict__ src, const int* __restrict__ dst,
                          int* cursor, int* ssrc, int e) {
    int i = blockIdx.x * blockDim.x + threadIdx.x;
    if (i < e) {
        int p = atomicAdd(&cursor[dst[i]], 1);
        ssrc[p] = src[i];
    }
}

// ---------------- graph aggregation (mean + max), warp per node ---------------
__global__ void k_agg(const float* __restrict__ h, const int* __restrict__ rowptr,
                      const int* __restrict__ ssrc, float* __restrict__ meanout,
                      float* __restrict__ maxout, int n) {
    int warp = (blockIdx.x * blockDim.x + threadIdx.x) >> 5;
    int lane = threadIdx.x & 31;
    if (warp >= n) return;
    int beg = rowptr[warp], end = rowptr[warp + 1];
    float4 s  = make_float4(0.f, 0.f, 0.f, 0.f);
    float4 mx = make_float4(-CUDART_INF_F, -CUDART_INF_F, -CUDART_INF_F, -CUDART_INF_F);
    for (int i = beg; i < end; i++) {
        int src = ssrc[i];
        float4 v = ((const float4*)(h + (size_t)src * DD))[lane];
        s.x += v.x; s.y += v.y; s.z += v.z; s.w += v.w;
        mx.x = fmaxf(mx.x, v.x); mx.y = fmaxf(mx.y, v.y);
        mx.z = fmaxf(mx.z, v.z); mx.w = fmaxf(mx.w, v.w);
    }
    int deg = end - beg;
    float inv = 1.0f / (float)max(deg, 1);
    float4 mo = make_float4(s.x * inv, s.y * inv, s.z * inv, s.w * inv);
    float4 xo = (deg > 0) ? mx : make_float4(0.f, 0.f, 0.f, 0.f);
    ((float4*)(meanout + (size_t)warp * DD))[lane] = mo;
    ((float4*)(maxout  + (size_t)warp * DD))[lane] = xo;
}

// ---------------- mixed epilogue: normalize + relu + weighted k-sum (float4) ---
__global__ void k_combine(const float* __restrict__ y, const float* __restrict__ stats,
                          const float* __restrict__ wrow, const float* __restrict__ gg,
                          const float* __restrict__ be, float* __restrict__ out,
                          int n, int accum) {
    int i4 = blockIdx.x * blockDim.x + threadIdx.x;
    int total4 = (n * DD) >> 2;
    if (i4 >= total4) return;
    int d0 = (i4 << 2) & (DD - 1);
    float fn = (float)n;
    float4 acc = make_float4(0.f, 0.f, 0.f, 0.f);
    #pragma unroll
    for (int k = 0; k < 3; k++) {
        float wk = wrow[k];
        float4 v = ((const float4*)(y + (size_t)k * n * DD))[i4];
        #pragma unroll
        for (int j = 0; j < 4; j++) {
            int d = d0 + j;
            float mu  = stats[k * DD + d] / fn;
            float var = stats[3 * DD + k * DD + d] / fn - mu * mu;
            float rs  = rsqrtf(var + EPSLN);
            float vv = (&v.x)[j];
            float t = (vv - mu) * rs * gg[k * DD + d] + be[k * DD + d];
            (&acc.x)[j] += wk * fmaxf(t, 0.f);
        }
    }
    if (accum) {
        float4 o = ((float4*)out)[i4];
        acc.x += o.x; acc.y += o.y; acc.z += o.z; acc.w += o.w;
    }
    ((float4*)out)[i4] = acc;
}

// ---------------- final column-norm + relu ------------------------------------
__global__ void k_finalnorm(const float* __restrict__ h, const float* __restrict__ stats,
                            const float* __restrict__ gc, const float* __restrict__ bec,
                            float* __restrict__ out, int n) {
    int idx = blockIdx.x * blockDim.x + threadIdx.x;
    int total = n * DD;
    if (idx >= total) return;
    int d = idx & (DD - 1);
    float fn = (float)n;
    float mu  = stats[d] / fn;
    float var = stats[3 * DD + d] / fn - mu * mu;
    float rs  = rsqrtf(var + EPSLN);
    float v = (h[idx] - mu) * rs * gc[d] + bec[d];
    out[idx] = fmaxf(v, 0.f);
}

// ---------------- host orchestration ------------------------------------------
extern "C" void kernel_launch(void* const* d_in, const int* in_sizes, int n_in,
                              void* d_out, int out_size) {
    const float* src_emb = (const float*)d_in[0];
    const float* hr      = (const float*)d_in[1];
    const int*   esrc    = (const int*)d_in[2];
    const int*   edst    = (const int*)d_in[3];
    const float* w_zero  = (const float*)d_in[4];
    const float* w_first = (const float*)d_in[5];
    const float* w_mid   = (const float*)d_in[6];
    const float* w_last  = (const float*)d_in[7];
    const float* W_zero  = (const float*)d_in[8];
    const float* b_zero  = (const float*)d_in[9];
    const float* g_zeroP = (const float*)d_in[10];
    const float* be_zero = (const float*)d_in[11];
    const float* W_first = (const float*)d_in[12];
    const float* b_first = (const float*)d_in[13];
    const float* g_firstP= (const float*)d_in[14];
    const float* be_first= (const float*)d_in[15];
    const float* W_mid   = (const float*)d_in[16];
    const float* b_mid   = (const float*)d_in[17];
    const float* g_midP  = (const float*)d_in[18];
    const float* be_mid  = (const float*)d_in[19];
    const float* W_last  = (const float*)d_in[20];
    const float* b_last  = (const float*)d_in[21];
    const float* g_lastP = (const float*)d_in[22];
    const float* be_last = (const float*)d_in[23];
    const float* W_cat   = (const float*)d_in[24];
    const float* b_cat   = (const float*)d_in[25];
    const float* g_cat   = (const float*)d_in[26];
    const float* be_cat  = (const float*)d_in[27];

    int n = in_sizes[0] / DD;
    int e = in_sizes[2];

    float *yb, *hin, *s0, *s1, *m0, *m1, *sl, *mean, *mx, *statsA;
    int *deg, *rowptr, *cursor, *ssrc, *bsums;
    __half* wpre;
    cudaGetSymbolAddress((void**)&yb, g_y);
    cudaGetSymbolAddress((void**)&hin, g_hin);
    cudaGetSymbolAddress((void**)&s0, g_s0);
    cudaGetSymbolAddress((void**)&s1, g_s1);
    cudaGetSymbolAddress((void**)&m0, g_m0);
    cudaGetSymbolAddress((void**)&m1, g_m1);
    cudaGetSymbolAddress((void**)&sl, g_slast);
    cudaGetSymbolAddress((void**)&mean, g_mean);
    cudaGetSymbolAddress((void**)&mx, g_max);
    cudaGetSymbolAddress((void**)&statsA, g_statsA);
    cudaGetSymbolAddress((void**)&deg, g_deg);
    cudaGetSymbolAddress((void**)&rowptr, g_rowptr);
    cudaGetSymbolAddress((void**)&cursor, g_cursor);
    cudaGetSymbolAddress((void**)&ssrc, g_ssrc);
    cudaGetSymbolAddress((void**)&bsums, g_bsums);
    cudaGetSymbolAddress((void**)&wpre, g_wpre);

    cudaFuncSetAttribute(k_gemm_mma, cudaFuncAttributeMaxDynamicSharedMemorySize, SMEM_MMA);

    int total = n * DD;
    size_t ystride = (size_t)n * DD;
    int gtiles = (n + 127) / 128;
    int ew_grid = (total + 255) / 256;
    int ew_grid4 = (total / 4 + 255) / 256;
    int agg_grid = (n + 7) / 8;
    int eb = (e + 255) / 256;
    int nb1024 = (n + 1023) / 1024;

    // ---- weight prep (stats slots zeroed in first launch) ----
    k_wprep<<<3 * 8, 256>>>(W_zero,  wpre + 0L  * 16384, statsA, 9 * 768);
    k_wprep<<<9 * 8, 256>>>(W_first, wpre + 3L  * 16384, nullptr, 0);
    k_wprep<<<6 * 8, 256>>>(W_mid,   wpre + 12L * 16384, nullptr, 0);
    k_wprep<<<6 * 8, 256>>>(W_last,  wpre + 18L * 16384, nullptr, 0);
    k_wprep<<<3 * 8, 256>>>(W_cat,   wpre + 24L * 16384, nullptr, 0);

    int slot = 0;
    auto run_mixed = [&](const float* x0, const float* x1, const float* x2,
                         int opmat, const float* B, const float* G, const float* BE,
                         const float* wrow, float* out, int accum, int premode) {
        float* st = statsA + (size_t)slot * 768;
        slot++;
        k_gemm_mma<<<dim3(gtiles, 1, 3), 256, SMEM_MMA>>>(
            x0, x1, x2, wpre + (size_t)opmat * 16384, B, yb, st, n, ystride, 0, premode);
        k_combine<<<ew_grid4, 256>>>(yb, st, wrow, G, BE, out, n, accum);
    };

    // ---- zero op (pre fused into GEMM fill) ----
    run_mixed(src_emb, hr, nullptr, 0, b_zero, g_zeroP, be_zero, w_zero, hin, 0, 1);

    // ---- CSR build ----
    cudaMemsetAsync(deg, 0, (size_t)n * sizeof(int));
    k_hist<<<eb, 256>>>(edst, deg, e);
    k_scan_block<<<nb1024, 1024>>>(deg, cursor, bsums, n);
    k_scan_sums<<<1, 32>>>(bsums, nb1024);
    k_scan_fin<<<(n + 255) / 256, 256>>>(deg, cursor, bsums, rowptr, cursor, n, e);
    k_scatter<<<eb, 256>>>(esrc, edst, cursor, ssrc, e);

    // ---- first ops ----
    k_agg<<<agg_grid, 256>>>(hin, rowptr, ssrc, mean, mx, n);
    run_mixed(hin, mean, mx, 3, b_first + 0 * 3 * DD, g_firstP + 0 * 3 * DD,
              be_first + 0 * 3 * DD, w_first + 0 * 3, s0, 0, 0);
    run_mixed(hin, mean, mx, 6, b_first + 1 * 3 * DD, g_firstP + 1 * 3 * DD,
              be_first + 1 * 3 * DD, w_first + 1 * 3, s1, 0, 0);
    k_agg<<<agg_grid, 256>>>(s0, rowptr, ssrc, mean, mx, n);
    run_mixed(s0, mean, mx, 9, b_first + 2 * 3 * DD, g_firstP + 2 * 3 * DD,
              be_first + 2 * 3 * DD, w_first + 2 * 3, s1, 1, 0);

    // ---- middle ops ----
    run_mixed(s0, mean, mx, 12, b_mid + 0 * 3 * DD, g_midP + 0 * 3 * DD,
              be_mid + 0 * 3 * DD, w_mid + 0 * 3, m0, 0, 0);
    k_agg<<<agg_grid, 256>>>(s1, rowptr, ssrc, mean, mx, n);
    run_mixed(s1, mean, mx, 15, b_mid + 1 * 3 * DD, g_midP + 1 * 3 * DD,
              be_mid + 1 * 3 * DD, w_mid + 1 * 3, m1, 0, 0);

    // ---- last ops ----
    k_agg<<<agg_grid, 256>>>(m0, rowptr, ssrc, mean, mx, n);
    run_mixed(m0, mean, mx, 18, b_last + 0 * 3 * DD, g_lastP + 0 * 3 * DD,
              be_last + 0 * 3 * DD, w_last + 0 * 3, sl, 0, 0);
    k_agg<<<agg_grid, 256>>>(m1, rowptr, ssrc, mean, mx, n);
    run_mixed(m1, mean, mx, 21, b_last + 1 * 3 * DD, g_lastP + 1 * 3 * DD,
              be_last + 1 * 3 * DD, w_last + 1 * 3, sl, 1, 0);

    // ---- final: cat GEMM (3 K-chunks) + column-norm ----
    {
        float* st = statsA + (size_t)8 * 768;
        k_gemm_mma<<<dim3(gtiles, 1, 1), 256, SMEM_MMA>>>(
            m0, m1, sl, wpre + 24L * 16384, b_cat, yb, st, n, ystride, 1, 0);
        k_finalnorm<<<ew_grid, 256>>>(yb, st, g_cat, be_cat, (float*)d_out, n);
    }
}

// round 9
// speedup vs baseline: 1.2948x; 1.2948x over previous
#include <cuda_runtime.h>
#include <cuda_fp16.h>
#include <cstdint>
#include <math_constants.h>

#define NN 100000
#define EE 600000
#define DD 128
#define EPSLN 1e-5f
#define PADK 72    // smem row stride in halves for 64-col tiles (144B, conflict-free ldmatrix)
#define PLANE ((size_t)(NN + 128) * DD)   // padded hi/lo plane (tail rows read as 0)

// ---------------- scratch (device globals) -------------------------------------
__device__ float g_y[3L * NN * DD];
__device__ float g_hin[(size_t)NN * DD];
__device__ float g_s0[(size_t)NN * DD];
__device__ float g_s1[(size_t)NN * DD];
__device__ float g_m0[(size_t)NN * DD];
__device__ float g_m1[(size_t)NN * DD];
__device__ float g_slast[(size_t)NN * DD];
__device__ float g_statsA[9 * 2 * 3 * DD];   // 9 op slots x (sum, sumsq) x 3 x 128
__device__ int   g_deg[NN];
__device__ int   g_rowptr[NN + 1];
__device__ int   g_cursor[NN];
__device__ int   g_ssrc[EE];
__device__ int   g_bsums[256];
__device__ __half g_wpre[27L * 16384];       // per matrix: fp16 W^T [f*128+d]
// hi/lo candidate planes; slots: 0=tmp 1=mean 2=max 3=hin 4=s0 5=s1 6=m0 7=m1 8=sl
__device__ __half g_hlhi[9 * PLANE];
__device__ __half g_hllo[9 * PLANE];

// ---------------- helpers ------------------------------------------------------
__device__ __forceinline__ uint32_t smem_u32(const void* p) {
    uint32_t a;
    asm("{ .reg .u64 t; cvta.to.shared.u64 t, %1; cvt.u32.u64 %0, t; }" : "=r"(a) : "l"(p));
    return a;
}
__device__ __forceinline__ uint32_t pkh(__half a, __half b) {
    return (uint32_t)__half_as_ushort(a) | ((uint32_t)__half_as_ushort(b) << 16);
}
__device__ __forceinline__ void split4(float4 v, uint2& hi, uint2& lo) {
    __half h0 = __float2half_rn(v.x), h1 = __float2half_rn(v.y);
    __half h2 = __float2half_rn(v.z), h3 = __float2half_rn(v.w);
    __half l0 = __float2half_rn(v.x - __half2float(h0));
    __half l1 = __float2half_rn(v.y - __half2float(h1));
    __half l2 = __float2half_rn(v.z - __half2float(h2));
    __half l3 = __float2half_rn(v.w - __half2float(h3));
    hi = make_uint2(pkh(h0, h1), pkh(h2, h3));
    lo = make_uint2(pkh(l0, l1), pkh(l2, l3));
}
__device__ __forceinline__ void ldsm_x4(uint32_t& r0, uint32_t& r1, uint32_t& r2, uint32_t& r3,
                                        uint32_t addr) {
    asm volatile("ldmatrix.sync.aligned.m8n8.x4.shared.b16 {%0, %1, %2, %3}, [%4];"
                 : "=r"(r0), "=r"(r1), "=r"(r2), "=r"(r3) : "r"(addr));
}
__device__ __forceinline__ void mma16816h(float* c, const uint32_t* a, const uint32_t* b) {
    asm volatile(
        "mma.sync.aligned.m16n8k16.row.col.f32.f16.f16.f32 "
        "{%0, %1, %2, %3}, {%4, %5, %6, %7}, {%8, %9}, {%0, %1, %2, %3};"
        : "+f"(c[0]), "+f"(c[1]), "+f"(c[2]), "+f"(c[3])
        : "r"(a[0]), "r"(a[1]), "r"(a[2]), "r"(a[3]), "r"(b[0]), "r"(b[1]));
}
__device__ __forceinline__ void cpasync16(uint32_t saddr, const void* gaddr) {
    asm volatile("cp.async.cg.shared.global [%0], [%1], 16;" :: "r"(saddr), "l"(gaddr));
}
__device__ __forceinline__ void cpasync_waitall() {
    asm volatile("cp.async.commit_group;");
    asm volatile("cp.async.wait_group 0;");
}

// ---------------- weight prep: W[d][f] fp32 -> fp16 W^T[f][d] -------------------
__global__ void k_wprep(const float* __restrict__ W, __half* __restrict__ out,
                        float* statszero, int zn) {
    if (statszero && blockIdx.x == 0) {
        for (int i = threadIdx.x; i < zn; i += blockDim.x) statszero[i] = 0.f;
    }
    int m = blockIdx.x >> 3;
    int part = blockIdx.x & 7;
    const float* src = W + (size_t)m * 16384;
    __half* oh = out + (size_t)m * 16384;
    int base = part * 2048;
    for (int i = threadIdx.x; i < 2048; i += blockDim.x) {
        int idx = base + i;
        int d = idx >> 7, f = idx & 127;
        oh[f * 128 + d] = __float2half_rn(src[idx]);
    }
}

// ---------------- zero-op candidates -> hi/lo planes ---------------------------
__global__ void k_pre_hl(const float* __restrict__ a, const float* __restrict__ b,
                         __half* h0, __half* l0, __half* h1, __half* l1,
                         __half* h2, __half* l2, int total4) {
    int i4 = blockIdx.x * blockDim.x + threadIdx.x;
    if (i4 >= total4) return;
    float4 x = ((const float4*)a)[i4];
    float4 y = ((const float4*)b)[i4];
    uint2 hi, lo;
    split4(x, hi, lo);
    ((uint2*)h0)[i4] = hi; ((uint2*)l0)[i4] = lo;
    float4 d = make_float4(x.x - y.x, x.y - y.y, x.z - y.z, x.w - y.w);
    split4(d, hi, lo);
    ((uint2*)h1)[i4] = hi; ((uint2*)l1)[i4] = lo;
    float4 p = make_float4(x.x * y.x, x.y * y.y, x.z * y.z, x.w * y.w);
    split4(p, hi, lo);
    ((uint2*)h2)[i4] = hi; ((uint2*)l2)[i4] = lo;
}

// ---------------- fp16 2-pass tensor GEMM + fused column stats ------------------
// A fill is pure cp.async from pre-split hi/lo planes. 256 thr, 8 warps 4x2,
// warp tile 32x64; K in two 64-chunks; 2 CTAs/SM.
#define TILE_HALVES (128 * PADK)             // 9216 halves = 18432 B
#define SMEM_MMA (3 * TILE_HALVES * 2 + 1024)

__global__ __launch_bounds__(256, 2) void k_gemm_mma(
    const __half* __restrict__ xh0, const __half* __restrict__ xl0,
    const __half* __restrict__ xh1, const __half* __restrict__ xl1,
    const __half* __restrict__ xh2, const __half* __restrict__ xl2,
    const __half* __restrict__ wpre, const float* __restrict__ bias,
    float* __restrict__ Y, float* __restrict__ stats, int n, size_t ystride, int catmode)
{
    extern __shared__ char sm[];
    __half* Ahi = (__half*)sm;
    __half* Alo = Ahi + TILE_HALVES;
    __half* Bh  = Alo + TILE_HALVES;
    float* ssum = (float*)(Bh + TILE_HALVES);
    float* ssq  = ssum + 128;

    int tid = threadIdx.x;
    int wid = tid >> 5, lane = tid & 31;
    int wm_ = wid >> 1, wn_ = wid & 1;
    int kcand = catmode ? 0 : blockIdx.z;
    int nchunk = catmode ? 3 : 1;
    int row0 = blockIdx.x * 128;
    float* Yk = Y + (size_t)kcand * ystride;
    const float* bk = bias + kcand * DD;
    int so = kcand * DD;

    if (tid < 128) { ssum[tid] = 0.f; ssq[tid] = 0.f; }

    float c[2][8][4];
    #pragma unroll
    for (int i = 0; i < 2; i++)
        #pragma unroll
        for (int j = 0; j < 8; j++)
            #pragma unroll
            for (int q = 0; q < 4; q++) c[i][j][q] = 0.f;

    int a_row = wm_ * 32 + (lane & 15);
    int a_k8 = (lane >> 4) * 8;
    int b_f = wn_ * 64 + ((lane >> 4) << 3) + (lane & 7);
    int b_k8 = ((lane >> 3) & 1) * 8;
    uint32_t uAhi = smem_u32(Ahi), uAlo = smem_u32(Alo);
    uint32_t uBh = smem_u32(Bh);

    const __half* XH = (kcand == 0) ? xh0 : (kcand == 1 ? xh1 : xh2);
    const __half* XL = (kcand == 0) ? xl0 : (kcand == 1 ? xl1 : xl2);

    for (int c3 = 0; c3 < nchunk; c3++) {
        if (catmode) {
            XH = (c3 == 0) ? xh0 : (c3 == 1 ? xh1 : xh2);
            XL = (c3 == 0) ? xl0 : (c3 == 1 ? xl1 : xl2);
        }
        const __half* wm = wpre + (size_t)(catmode ? c3 : kcand) * 16384;

        for (int ch = 0; ch < 2; ch++) {          // K chunks of 64
            if (c3 + ch > 0) __syncthreads();     // prior mma reads done before refill

            int row = tid >> 1, sg = tid & 1;     // 2 threads/row, 64B each per plane
            size_t gofs = ((size_t)(row0 + row) * DD + ch * 64) * 2 + sg * 64;
            uint32_t sofs = (uint32_t)(row * PADK * 2 + sg * 64);
            // B tile
            {
                const char* sb = (const char*)wm + ((size_t)row * 128 + ch * 64) * 2 + sg * 64;
                uint32_t dst = uBh + sofs;
                #pragma unroll
                for (int q = 0; q < 4; q++) cpasync16(dst + q * 16, sb + q * 16);
            }
            // A hi / lo tiles (pure copies, planes are pre-split & padded)
            {
                const char* sh = (const char*)XH + gofs;
                const char* sl = (const char*)XL + gofs;
                uint32_t dh = uAhi + sofs, dl = uAlo + sofs;
                #pragma unroll
                for (int q = 0; q < 4; q++) {
                    cpasync16(dh + q * 16, sh + q * 16);
                    cpasync16(dl + q * 16, sl + q * 16);
                }
            }
            cpasync_waitall();
            __syncthreads();

            // 2 fp16 passes per k-step: hi_a*b + lo_a*b (B regs reused)
            #pragma unroll
            for (int k = 0; k < 4; k++) {
                uint32_t ah[2][4], al[2][4];
                #pragma unroll
                for (int mt = 0; mt < 2; mt++) {
                    uint32_t off = (uint32_t)(((a_row + mt * 16) * PADK + k * 16 + a_k8) * 2);
                    ldsm_x4(ah[mt][0], ah[mt][1], ah[mt][2], ah[mt][3], uAhi + off);
                    ldsm_x4(al[mt][0], al[mt][1], al[mt][2], al[mt][3], uAlo + off);
                }
                uint32_t b[4][4];
                #pragma unroll
                for (int p = 0; p < 4; p++) {
                    uint32_t addr = uBh + (uint32_t)(((b_f + p * 16) * PADK + k * 16 + b_k8) * 2);
                    ldsm_x4(b[p][0], b[p][1], b[p][2], b[p][3], addr);
                }
                #pragma unroll
                for (int mt = 0; mt < 2; mt++)
                    #pragma unroll
                    for (int nt = 0; nt < 8; nt++) {
                        mma16816h(c[mt][nt], ah[mt], &b[nt >> 1][(nt & 1) * 2]);
                        mma16816h(c[mt][nt], al[mt], &b[nt >> 1][(nt & 1) * 2]);
                    }
            }
        }
    }

    // ---------------- epilogue: bias, store Y, fused column stats ---------------
    int erow = lane >> 2, ecp = lane & 3;
    float2 bb[8];
    #pragma unroll
    for (int nt = 0; nt < 8; nt++)
        bb[nt] = *(const float2*)(bk + wn_ * 64 + nt * 8 + ecp * 2);

    float lsum[16], lsq[16];
    #pragma unroll
    for (int j = 0; j < 16; j++) { lsum[j] = 0.f; lsq[j] = 0.f; }

    #pragma unroll
    for (int mt = 0; mt < 2; mt++) {
        int r0g = row0 + wm_ * 32 + mt * 16 + erow;
        int r1g = r0g + 8;
        #pragma unroll
        for (int nt = 0; nt < 8; nt++) {
            int cbase = wn_ * 64 + nt * 8 + ecp * 2;
            float v00 = c[mt][nt][0] + bb[nt].x;
            float v01 = c[mt][nt][1] + bb[nt].y;
            float v10 = c[mt][nt][2] + bb[nt].x;
            float v11 = c[mt][nt][3] + bb[nt].y;
            if (r0g < n) {
                *(float2*)(Yk + (size_t)r0g * DD + cbase) = make_float2(v00, v01);
                lsum[nt * 2]     += v00; lsq[nt * 2]     += v00 * v00;
                lsum[nt * 2 + 1] += v01; lsq[nt * 2 + 1] += v01 * v01;
            }
            if (r1g < n) {
                *(float2*)(Yk + (size_t)r1g * DD + cbase) = make_float2(v10, v11);
                lsum[nt * 2]     += v10; lsq[nt * 2]     += v10 * v10;
                lsum[nt * 2 + 1] += v11; lsq[nt * 2 + 1] += v11 * v11;
            }
        }
    }
    #pragma unroll
    for (int nt = 0; nt < 8; nt++) {
        int cbase = wn_ * 64 + nt * 8 + ecp * 2;
        atomicAdd(&ssum[cbase],     lsum[nt * 2]);
        atomicAdd(&ssq[cbase],      lsq[nt * 2]);
        atomicAdd(&ssum[cbase + 1], lsum[nt * 2 + 1]);
        atomicAdd(&ssq[cbase + 1],  lsq[nt * 2 + 1]);
    }
    __syncthreads();
    if (tid < 128) {
        atomicAdd(&stats[so + tid], ssum[tid]);
        atomicAdd(&stats[3 * DD + so + tid], ssq[tid]);
    }
}

// ---------------- CSR build ---------------------------------------------------
__global__ void k_hist(const int* __restrict__ dst, int* deg, int e) {
    int i = blockIdx.x * blockDim.x + threadIdx.x;
    if (i < e) atomicAdd(&deg[dst[i]], 1);
}
__global__ void k_scan_block(const int* __restrict__ deg, int* incl, int* bsums, int n) {
    __shared__ int sh[1024];
    int i = blockIdx.x * 1024 + threadIdx.x;
    int v = (i < n) ? deg[i] : 0;
    sh[threadIdx.x] = v;
    __syncthreads();
    for (int off = 1; off < 1024; off <<= 1) {
        int t = (threadIdx.x >= off) ? sh[threadIdx.x - off] : 0;
        __syncthreads();
        sh[threadIdx.x] += t;
        __syncthreads();
    }
    if (i < n) incl[i] = sh[threadIdx.x];
    if (threadIdx.x == 1023) bsums[blockIdx.x] = sh[1023];
}
__global__ void k_scan_sums(int* bsums, int nb) {
    if (threadIdx.x == 0 && blockIdx.x == 0) {
        int run = 0;
        for (int i = 0; i < nb; i++) { int t = bsums[i]; bsums[i] = run; run += t; }
    }
}
__global__ void k_scan_fin(const int* __restrict__ deg, const int* __restrict__ incl,
                           const int* __restrict__ bsums, int* rowptr, int* cursor, int n, int e) {
    int i = blockIdx.x * blockDim.x + threadIdx.x;
    if (i < n) {
        int ex = incl[i] - deg[i] + bsums[i >> 10];
        rowptr[i] = ex;
        cursor[i] = ex;
        if (i == n - 1) rowptr[n] = e;
    }
}
__global__ void k_scatter(const int* __restrict__ src, const int* __restrict__ dst,
                          int* cursor, int* ssrc, int e) {
    int i = blockIdx.x * blockDim.x + threadIdx.x;
    if (i < e) {
        int p = atomicAdd(&cursor[dst[i]], 1);
        ssrc[p] = src[i];
    }
}

// ---------------- graph aggregation -> hi/lo planes, warp per node -------------
__global__ void k_agg(const float* __restrict__ h, const int* __restrict__ rowptr,
                      const int* __restrict__ ssrc,
                      __half* mhi, __half* mlo, __half* xhi, __half* xlo, int n) {
    int warp = (blockIdx.x * blockDim.x + threadIdx.x) >> 5;
    int lane = threadIdx.x & 31;
    if (warp >= n) return;
    int beg = rowptr[warp], end = rowptr[warp + 1];
    float4 s  = make_float4(0.f, 0.f, 0.f, 0.f);
    float4 mx = make_float4(-CUDART_INF_F, -CUDART_INF_F, -CUDART_INF_F, -CUDART_INF_F);
    for (int i = beg; i < end; i++) {
        int src = ssrc[i];
        float4 v = ((const float4*)(h + (size_t)src * DD))[lane];
        s.x += v.x; s.y += v.y; s.z += v.z; s.w += v.w;
        mx.x = fmaxf(mx.x, v.x); mx.y = fmaxf(mx.y, v.y);
        mx.z = fmaxf(mx.z, v.z); mx.w = fmaxf(mx.w, v.w);
    }
    int deg = end - beg;
    float inv = 1.0f / (float)max(deg, 1);
    float4 mo = make_float4(s.x * inv, s.y * inv, s.z * inv, s.w * inv);
    float4 xo = (deg > 0) ? mx : make_float4(0.f, 0.f, 0.f, 0.f);
    uint2 hi, lo;
    split4(mo, hi, lo);
    ((uint2*)(mhi + (size_t)warp * DD))[lane] = hi;
    ((uint2*)(mlo + (size_t)warp * DD))[lane] = lo;
    split4(xo, hi, lo);
    ((uint2*)(xhi + (size_t)warp * DD))[lane] = hi;
    ((uint2*)(xlo + (size_t)warp * DD))[lane] = lo;
}

// ---------------- mixed epilogue: normalize+relu+ksum; emits state + hl planes --
__global__ void k_combine(const float* __restrict__ y, const float* __restrict__ stats,
                          const float* __restrict__ wrow, const float* __restrict__ gg,
                          const float* __restrict__ be, float* __restrict__ out,
                          __half* hiP, __half* loP, int n, int accum, int writehl) {
    int i4 = blockIdx.x * blockDim.x + threadIdx.x;
    int total4 = (n * DD) >> 2;
    if (i4 >= total4) return;
    int d0 = (i4 << 2) & (DD - 1);
    float fn = (float)n;
    float4 acc = make_float4(0.f, 0.f, 0.f, 0.f);
    #pragma unroll
    for (int k = 0; k < 3; k++) {
        float wk = wrow[k];
        float4 v = ((const float4*)(y + (size_t)k * n * DD))[i4];
        #pragma unroll
        for (int j = 0; j < 4; j++) {
            int d = d0 + j;
            float mu  = stats[k * DD + d] / fn;
            float var = stats[3 * DD + k * DD + d] / fn - mu * mu;
            float rs  = rsqrtf(var + EPSLN);
            float vv = (&v.x)[j];
            float t = (vv - mu) * rs * gg[k * DD + d] + be[k * DD + d];
            (&acc.x)[j] += wk * fmaxf(t, 0.f);
        }
    }
    if (accum) {
        float4 o = ((float4*)out)[i4];
        acc.x += o.x; acc.y += o.y; acc.z += o.z; acc.w += o.w;
    }
    ((float4*)out)[i4] = acc;
    if (writehl) {
        uint2 hi, lo;
        split4(acc, hi, lo);
        ((uint2*)hiP)[i4] = hi;
        ((uint2*)loP)[i4] = lo;
    }
}

// ---------------- final column-norm + relu ------------------------------------
__global__ void k_finalnorm(const float* __restrict__ h, const float* __restrict__ stats,
                            const float* __restrict__ gc, const float* __restrict__ bec,
                            float* __restrict__ out, int n) {
    int idx = blockIdx.x * blockDim.x + threadIdx.x;
    int total = n * DD;
    if (idx >= total) return;
    int d = idx & (DD - 1);
    float fn = (float)n;
    float mu  = stats[d] / fn;
    float var = stats[3 * DD + d] / fn - mu * mu;
    float rs  = rsqrtf(var + EPSLN);
    float v = (h[idx] - mu) * rs * gc[d] + bec[d];
    out[idx] = fmaxf(v, 0.f);
}

// ---------------- host orchestration ------------------------------------------
extern "C" void kernel_launch(void* const* d_in, const int* in_sizes, int n_in,
                              void* d_out, int out_size) {
    const float* src_emb = (const float*)d_in[0];
    const float* hr      = (const float*)d_in[1];
    const int*   esrc    = (const int*)d_in[2];
    const int*   edst    = (const int*)d_in[3];
    const float* w_zero  = (const float*)d_in[4];
    const float* w_first = (const float*)d_in[5];
    const float* w_mid   = (const float*)d_in[6];
    const float* w_last  = (const float*)d_in[7];
    const float* W_zero  = (const float*)d_in[8];
    const float* b_zero  = (const float*)d_in[9];
    const float* g_zeroP = (const float*)d_in[10];
    const float* be_zero = (const float*)d_in[11];
    const float* W_first = (const float*)d_in[12];
    const float* b_first = (const float*)d_in[13];
    const float* g_firstP= (const float*)d_in[14];
    const float* be_first= (const float*)d_in[15];
    const float* W_mid   = (const float*)d_in[16];
    const float* b_mid   = (const float*)d_in[17];
    const float* g_midP  = (const float*)d_in[18];
    const float* be_mid  = (const float*)d_in[19];
    const float* W_last  = (const float*)d_in[20];
    const float* b_last  = (const float*)d_in[21];
    const float* g_lastP = (const float*)d_in[22];
    const float* be_last = (const float*)d_in[23];
    const float* W_cat   = (const float*)d_in[24];
    const float* b_cat   = (const float*)d_in[25];
    const float* g_cat   = (const float*)d_in[26];
    const float* be_cat  = (const float*)d_in[27];

    int n = in_sizes[0] / DD;
    int e = in_sizes[2];

    float *yb, *hin, *s0, *s1, *m0, *m1, *sl, *statsA;
    int *deg, *rowptr, *cursor, *ssrc, *bsums;
    __half *wpre, *hlhi, *hllo;
    cudaGetSymbolAddress((void**)&yb, g_y);
    cudaGetSymbolAddress((void**)&hin, g_hin);
    cudaGetSymbolAddress((void**)&s0, g_s0);
    cudaGetSymbolAddress((void**)&s1, g_s1);
    cudaGetSymbolAddress((void**)&m0, g_m0);
    cudaGetSymbolAddress((void**)&m1, g_m1);
    cudaGetSymbolAddress((void**)&sl, g_slast);
    cudaGetSymbolAddress((void**)&statsA, g_statsA);
    cudaGetSymbolAddress((void**)&deg, g_deg);
    cudaGetSymbolAddress((void**)&rowptr, g_rowptr);
    cudaGetSymbolAddress((void**)&cursor, g_cursor);
    cudaGetSymbolAddress((void**)&ssrc, g_ssrc);
    cudaGetSymbolAddress((void**)&bsums, g_bsums);
    cudaGetSymbolAddress((void**)&wpre, g_wpre);
    cudaGetSymbolAddress((void**)&hlhi, g_hlhi);
    cudaGetSymbolAddress((void**)&hllo, g_hllo);

    cudaFuncSetAttribute(k_gemm_mma, cudaFuncAttributeMaxDynamicSharedMemorySize, SMEM_MMA);

    auto HI = [&](int s) { return hlhi + (size_t)s * PLANE; };
    auto LO = [&](int s) { return hllo + (size_t)s * PLANE; };

    int total = n * DD;
    size_t ystride = (size_t)n * DD;
    int gtiles = (n + 127) / 128;
    int ew_grid = (total + 255) / 256;
    int ew_grid4 = (total / 4 + 255) / 256;
    int agg_grid = (n + 7) / 8;
    int eb = (e + 255) / 256;
    int nb1024 = (n + 1023) / 1024;

    // ---- weight prep (stats slots zeroed in first launch) ----
    k_wprep<<<3 * 8, 256>>>(W_zero,  wpre + 0L  * 16384, statsA, 9 * 768);
    k_wprep<<<9 * 8, 256>>>(W_first, wpre + 3L  * 16384, nullptr, 0);
    k_wprep<<<6 * 8, 256>>>(W_mid,   wpre + 12L * 16384, nullptr, 0);
    k_wprep<<<6 * 8, 256>>>(W_last,  wpre + 18L * 16384, nullptr, 0);
    k_wprep<<<3 * 8, 256>>>(W_cat,   wpre + 24L * 16384, nullptr, 0);

    int slot = 0;
    auto run_mixed = [&](int c0, int c1, int c2,
                         int opmat, const float* B, const float* G, const float* BE,
                         const float* wrow, float* out, int accum, int hlslot) {
        float* st = statsA + (size_t)slot * 768;
        slot++;
        k_gemm_mma<<<dim3(gtiles, 1, 3), 256, SMEM_MMA>>>(
            HI(c0), LO(c0), HI(c1), LO(c1), HI(c2), LO(c2),
            wpre + (size_t)opmat * 16384, B, yb, st, n, ystride, 0);
        k_combine<<<ew_grid4, 256>>>(yb, st, wrow, G, BE, out,
                                     hlslot >= 0 ? HI(hlslot) : nullptr,
                                     hlslot >= 0 ? LO(hlslot) : nullptr,
                                     n, accum, hlslot >= 0 ? 1 : 0);
    };

    // ---- zero op: pre candidates into slots 0,1,2 ----
    k_pre_hl<<<ew_grid4, 256>>>(src_emb, hr, HI(0), LO(0), HI(1), LO(1), HI(2), LO(2), total / 4);
    run_mixed(0, 1, 2, 0, b_zero, g_zeroP, be_zero, w_zero, hin, 0, 3);

    // ---- CSR build ----
    cudaMemsetAsync(deg, 0, (size_t)n * sizeof(int));
    k_hist<<<eb, 256>>>(edst, deg, e);
    k_scan_block<<<nb1024, 1024>>>(deg, cursor, bsums, n);
    k_scan_sums<<<1, 32>>>(bsums, nb1024);
    k_scan_fin<<<(n + 255) / 256, 256>>>(deg, cursor, bsums, rowptr, cursor, n, e);
    k_scatter<<<eb, 256>>>(esrc, edst, cursor, ssrc, e);

    // ---- first ops ----
    k_agg<<<agg_grid, 256>>>(hin, rowptr, ssrc, HI(1), LO(1), HI(2), LO(2), n);
    run_mixed(3, 1, 2, 3, b_first + 0 * 3 * DD, g_firstP + 0 * 3 * DD,
              be_first + 0 * 3 * DD, w_first + 0 * 3, s0, 0, 4);
    run_mixed(3, 1, 2, 6, b_first + 1 * 3 * DD, g_firstP + 1 * 3 * DD,
              be_first + 1 * 3 * DD, w_first + 1 * 3, s1, 0, -1);
    k_agg<<<agg_grid, 256>>>(s0, rowptr, ssrc, HI(1), LO(1), HI(2), LO(2), n);
    run_mixed(4, 1, 2, 9, b_first + 2 * 3 * DD, g_firstP + 2 * 3 * DD,
              be_first + 2 * 3 * DD, w_first + 2 * 3, s1, 1, 5);

    // ---- middle ops ---- (agg(s0) still in slots 1,2)
    run_mixed(4, 1, 2, 12, b_mid + 0 * 3 * DD, g_midP + 0 * 3 * DD,
              be_mid + 0 * 3 * DD, w_mid + 0 * 3, m0, 0, 6);
    k_agg<<<agg_grid, 256>>>(s1, rowptr, ssrc, HI(1), LO(1), HI(2), LO(2), n);
    run_mixed(5, 1, 2, 15, b_mid + 1 * 3 * DD, g_midP + 1 * 3 * DD,
              be_mid + 1 * 3 * DD, w_mid + 1 * 3, m1, 0, 7);

    // ---- last ops ----
    k_agg<<<agg_grid, 256>>>(m0, rowptr, ssrc, HI(1), LO(1), HI(2), LO(2), n);
    run_mixed(6, 1, 2, 18, b_last + 0 * 3 * DD, g_lastP + 0 * 3 * DD,
              be_last + 0 * 3 * DD, w_last + 0 * 3, sl, 0, -1);
    k_agg<<<agg_grid, 256>>>(m1, rowptr, ssrc, HI(1), LO(1), HI(2), LO(2), n);
    run_mixed(7, 1, 2, 21, b_last + 1 * 3 * DD, g_lastP + 1 * 3 * DD,
              be_last + 1 * 3 * DD, w_last + 1 * 3, sl, 1, 8);

    // ---- final: cat GEMM (3 K-chunks over m0,m1,sl planes) + column-norm ----
    {
        float* st = statsA + (size_t)8 * 768;
        k_gemm_mma<<<dim3(gtiles, 1, 1), 256, SMEM_MMA>>>(
            HI(6), LO(6), HI(7), LO(7), HI(8), LO(8),
            wpre + 24L * 16384, b_cat, yb, st, n, ystride, 1);
        k_finalnorm<<<ew_grid, 256>>>(yb, st, g_cat, be_cat, (float*)d_out, n);
    }
}

// round 10
// speedup vs baseline: 1.3249x; 1.0232x over previous
#include <cuda_runtime.h>
#include <cuda_fp16.h>
#include <cstdint>
#include <math_constants.h>

#define NN 100000
#define EE 600000
#define DD 128
#define EPSLN 1e-5f
#define PADK 72    // smem row stride in halves for 64-col tiles (144B, conflict-free ldmatrix)
#define PLANE ((size_t)(NN + 128) * DD)   // padded hi/lo plane (tail rows read as 0)

// ---------------- scratch (device globals) -------------------------------------
__device__ float g_y[6L * NN * DD];          // 6 y planes (for z=6 batched GEMMs)
__device__ float g_statsA[9 * 2 * 3 * DD];   // 9 op slots x (sum, sumsq) x 3 x 128
__device__ int   g_deg[NN];
__device__ int   g_rowptr[NN + 1];
__device__ int   g_cursor[NN];
__device__ int   g_ssrc[EE];
__device__ int   g_bsums[256];
__device__ __half g_wpre[27L * 16384];       // per matrix: fp16 W^T [f*128+d]
// hi/lo candidate planes; slots: 0=pre0/aggB-mean 1=pre1/agg-mean 2=pre2/agg-max
//                                3=hin/aggB-max 4=s0 5=s1 6=m0 7=m1 8=sl
__device__ __half g_hlhi[9 * PLANE];
__device__ __half g_hllo[9 * PLANE];

// ---------------- helpers ------------------------------------------------------
__device__ __forceinline__ uint32_t smem_u32(const void* p) {
    uint32_t a;
    asm("{ .reg .u64 t; cvta.to.shared.u64 t, %1; cvt.u32.u64 %0, t; }" : "=r"(a) : "l"(p));
    return a;
}
__device__ __forceinline__ uint32_t pkh(__half a, __half b) {
    return (uint32_t)__half_as_ushort(a) | ((uint32_t)__half_as_ushort(b) << 16);
}
__device__ __forceinline__ void split4(float4 v, uint2& hi, uint2& lo) {
    __half h0 = __float2half_rn(v.x), h1 = __float2half_rn(v.y);
    __half h2 = __float2half_rn(v.z), h3 = __float2half_rn(v.w);
    __half l0 = __float2half_rn(v.x - __half2float(h0));
    __half l1 = __float2half_rn(v.y - __half2float(h1));
    __half l2 = __float2half_rn(v.z - __half2float(h2));
    __half l3 = __float2half_rn(v.w - __half2float(h3));
    hi = make_uint2(pkh(h0, h1), pkh(h2, h3));
    lo = make_uint2(pkh(l0, l1), pkh(l2, l3));
}
__device__ __forceinline__ float4 join4(uint2 hi, uint2 lo) {
    __half2 h01 = *(__half2*)&hi.x, h23 = *(__half2*)&hi.y;
    __half2 l01 = *(__half2*)&lo.x, l23 = *(__half2*)&lo.y;
    float2 a = __half22float2(h01), b = __half22float2(h23);
    float2 c = __half22float2(l01), d = __half22float2(l23);
    return make_float4(a.x + c.x, a.y + c.y, b.x + d.x, b.y + d.y);
}
__device__ __forceinline__ void ldsm_x4(uint32_t& r0, uint32_t& r1, uint32_t& r2, uint32_t& r3,
                                        uint32_t addr) {
    asm volatile("ldmatrix.sync.aligned.m8n8.x4.shared.b16 {%0, %1, %2, %3}, [%4];"
                 : "=r"(r0), "=r"(r1), "=r"(r2), "=r"(r3) : "r"(addr));
}
__device__ __forceinline__ void mma16816h(float* c, const uint32_t* a, const uint32_t* b) {
    asm volatile(
        "mma.sync.aligned.m16n8k16.row.col.f32.f16.f16.f32 "
        "{%0, %1, %2, %3}, {%4, %5, %6, %7}, {%8, %9}, {%0, %1, %2, %3};"
        : "+f"(c[0]), "+f"(c[1]), "+f"(c[2]), "+f"(c[3])
        : "r"(a[0]), "r"(a[1]), "r"(a[2]), "r"(a[3]), "r"(b[0]), "r"(b[1]));
}
__device__ __forceinline__ void cpasync16(uint32_t saddr, const void* gaddr) {
    asm volatile("cp.async.cg.shared.global [%0], [%1], 16;" :: "r"(saddr), "l"(gaddr));
}
__device__ __forceinline__ void cpasync_waitall() {
    asm volatile("cp.async.commit_group;");
    asm volatile("cp.async.wait_group 0;");
}

// ---------------- weight prep: W[d][f] fp32 -> fp16 W^T[f][d] -------------------
__global__ void k_wprep(const float* __restrict__ W, __half* __restrict__ out,
                        float* statszero, int zn) {
    if (statszero && blockIdx.x == 0) {
        for (int i = threadIdx.x; i < zn; i += blockDim.x) statszero[i] = 0.f;
    }
    int m = blockIdx.x >> 3;
    int part = blockIdx.x & 7;
    const float* src = W + (size_t)m * 16384;
    __half* oh = out + (size_t)m * 16384;
    int base = part * 2048;
    for (int i = threadIdx.x; i < 2048; i += blockDim.x) {
        int idx = base + i;
        int d = idx >> 7, f = idx & 127;
        oh[f * 128 + d] = __float2half_rn(src[idx]);
    }
}

// ---------------- zero-op candidates -> hi/lo planes ---------------------------
__global__ void k_pre_hl(const float* __restrict__ a, const float* __restrict__ b,
                         __half* h0, __half* l0, __half* h1, __half* l1,
                         __half* h2, __half* l2, int total4) {
    int i4 = blockIdx.x * blockDim.x + threadIdx.x;
    if (i4 >= total4) return;
    float4 x = ((const float4*)a)[i4];
    float4 y = ((const float4*)b)[i4];
    uint2 hi, lo;
    split4(x, hi, lo);
    ((uint2*)h0)[i4] = hi; ((uint2*)l0)[i4] = lo;
    float4 d = make_float4(x.x - y.x, x.y - y.y, x.z - y.z, x.w - y.w);
    split4(d, hi, lo);
    ((uint2*)h1)[i4] = hi; ((uint2*)l1)[i4] = lo;
    float4 p = make_float4(x.x * y.x, x.y * y.y, x.z * y.z, x.w * y.w);
    split4(p, hi, lo);
    ((uint2*)h2)[i4] = hi; ((uint2*)l2)[i4] = lo;
}

// ---------------- fp16 2-pass tensor GEMM + fused column stats ------------------
// Up to 2 ops per launch (z = 3*nops). Pure-cp.async A fill from hi/lo planes.
#define TILE_HALVES (128 * PADK)             // 9216 halves = 18432 B
#define SMEM_MMA (3 * TILE_HALVES * 2 + 1024)

__global__ __launch_bounds__(256, 2) void k_gemm_mma(
    const __half* __restrict__ a0h, const __half* __restrict__ a0l,
    const __half* __restrict__ a1h, const __half* __restrict__ a1l,
    const __half* __restrict__ a2h, const __half* __restrict__ a2l,
    const __half* __restrict__ b0h, const __half* __restrict__ b0l,
    const __half* __restrict__ b1h, const __half* __restrict__ b1l,
    const __half* __restrict__ b2h, const __half* __restrict__ b2l,
    const __half* __restrict__ wpre, const float* __restrict__ bias,
    float* __restrict__ Y, float* __restrict__ stats, int n, size_t ystride, int catmode)
{
    extern __shared__ char sm[];
    __half* Ahi = (__half*)sm;
    __half* Alo = Ahi + TILE_HALVES;
    __half* Bh  = Alo + TILE_HALVES;
    float* ssum = (float*)(Bh + TILE_HALVES);
    float* ssq  = ssum + 128;

    int tid = threadIdx.x;
    int wid = tid >> 5, lane = tid & 31;
    int wm_ = wid >> 1, wn_ = wid & 1;
    int z = blockIdx.z;
    int opsel = z / 3;
    int kcand = catmode ? 0 : (z % 3);
    int nchunk = catmode ? 3 : 1;
    int row0 = blockIdx.x * 128;
    float* Yk = Y + (size_t)(opsel * 3 + kcand) * ystride;
    const float* bk = bias + (opsel * 3 + kcand) * DD;
    float* st = stats + opsel * 768;
    int so = kcand * DD;

    if (tid < 128) { ssum[tid] = 0.f; ssq[tid] = 0.f; }

    float c[2][8][4];
    #pragma unroll
    for (int i = 0; i < 2; i++)
        #pragma unroll
        for (int j = 0; j < 8; j++)
            #pragma unroll
            for (int q = 0; q < 4; q++) c[i][j][q] = 0.f;

    int a_row = wm_ * 32 + (lane & 15);
    int a_k8 = (lane >> 4) * 8;
    int b_f = wn_ * 64 + ((lane >> 4) << 3) + (lane & 7);
    int b_k8 = ((lane >> 3) & 1) * 8;
    uint32_t uAhi = smem_u32(Ahi), uAlo = smem_u32(Alo);
    uint32_t uBh = smem_u32(Bh);

    const __half* XH;
    const __half* XL;
    if (opsel == 0) {
        XH = (kcand == 0) ? a0h : (kcand == 1 ? a1h : a2h);
        XL = (kcand == 0) ? a0l : (kcand == 1 ? a1l : a2l);
    } else {
        XH = (kcand == 0) ? b0h : (kcand == 1 ? b1h : b2h);
        XL = (kcand == 0) ? b0l : (kcand == 1 ? b1l : b2l);
    }

    for (int c3 = 0; c3 < nchunk; c3++) {
        if (catmode) {
            XH = (c3 == 0) ? a0h : (c3 == 1 ? a1h : a2h);
            XL = (c3 == 0) ? a0l : (c3 == 1 ? a1l : a2l);
        }
        const __half* wm = wpre + (size_t)(opsel * 3 + (catmode ? c3 : kcand)) * 16384;

        for (int ch = 0; ch < 2; ch++) {          // K chunks of 64
            if (c3 + ch > 0) __syncthreads();     // prior mma reads done before refill

            int row = tid >> 1, sg = tid & 1;     // 2 threads/row, 64B each per plane
            size_t gofs = ((size_t)(row0 + row) * DD + ch * 64) * 2 + sg * 64;
            uint32_t sofs = (uint32_t)(row * PADK * 2 + sg * 64);
            // B tile
            {
                const char* sb = (const char*)wm + ((size_t)row * 128 + ch * 64) * 2 + sg * 64;
                uint32_t dst = uBh + sofs;
                #pragma unroll
                for (int q = 0; q < 4; q++) cpasync16(dst + q * 16, sb + q * 16);
            }
            // A hi / lo tiles (pure copies)
            {
                const char* sh = (const char*)XH + gofs;
                const char* sl = (const char*)XL + gofs;
                uint32_t dh = uAhi + sofs, dl = uAlo + sofs;
                #pragma unroll
                for (int q = 0; q < 4; q++) {
                    cpasync16(dh + q * 16, sh + q * 16);
                    cpasync16(dl + q * 16, sl + q * 16);
                }
            }
            cpasync_waitall();
            __syncthreads();

            #pragma unroll
            for (int k = 0; k < 4; k++) {
                uint32_t ah[2][4], al[2][4];
                #pragma unroll
                for (int mt = 0; mt < 2; mt++) {
                    uint32_t off = (uint32_t)(((a_row + mt * 16) * PADK + k * 16 + a_k8) * 2);
                    ldsm_x4(ah[mt][0], ah[mt][1], ah[mt][2], ah[mt][3], uAhi + off);
                    ldsm_x4(al[mt][0], al[mt][1], al[mt][2], al[mt][3], uAlo + off);
                }
                uint32_t b[4][4];
                #pragma unroll
                for (int p = 0; p < 4; p++) {
                    uint32_t addr = uBh + (uint32_t)(((b_f + p * 16) * PADK + k * 16 + b_k8) * 2);
                    ldsm_x4(b[p][0], b[p][1], b[p][2], b[p][3], addr);
                }
                #pragma unroll
                for (int mt = 0; mt < 2; mt++)
                    #pragma unroll
                    for (int nt = 0; nt < 8; nt++) {
                        mma16816h(c[mt][nt], ah[mt], &b[nt >> 1][(nt & 1) * 2]);
                        mma16816h(c[mt][nt], al[mt], &b[nt >> 1][(nt & 1) * 2]);
                    }
            }
        }
    }

    // ---------------- epilogue: bias, store Y, fused column stats ---------------
    int erow = lane >> 2, ecp = lane & 3;
    float2 bb[8];
    #pragma unroll
    for (int nt = 0; nt < 8; nt++)
        bb[nt] = *(const float2*)(bk + wn_ * 64 + nt * 8 + ecp * 2);

    float lsum[16], lsq[16];
    #pragma unroll
    for (int j = 0; j < 16; j++) { lsum[j] = 0.f; lsq[j] = 0.f; }

    #pragma unroll
    for (int mt = 0; mt < 2; mt++) {
        int r0g = row0 + wm_ * 32 + mt * 16 + erow;
        int r1g = r0g + 8;
        #pragma unroll
        for (int nt = 0; nt < 8; nt++) {
            int cbase = wn_ * 64 + nt * 8 + ecp * 2;
            float v00 = c[mt][nt][0] + bb[nt].x;
            float v01 = c[mt][nt][1] + bb[nt].y;
            float v10 = c[mt][nt][2] + bb[nt].x;
            float v11 = c[mt][nt][3] + bb[nt].y;
            if (r0g < n) {
                *(float2*)(Yk + (size_t)r0g * DD + cbase) = make_float2(v00, v01);
                lsum[nt * 2]     += v00; lsq[nt * 2]     += v00 * v00;
                lsum[nt * 2 + 1] += v01; lsq[nt * 2 + 1] += v01 * v01;
            }
            if (r1g < n) {
                *(float2*)(Yk + (size_t)r1g * DD + cbase) = make_float2(v10, v11);
                lsum[nt * 2]     += v10; lsq[nt * 2]     += v10 * v10;
                lsum[nt * 2 + 1] += v11; lsq[nt * 2 + 1] += v11 * v11;
            }
        }
    }
    #pragma unroll
    for (int nt = 0; nt < 8; nt++) {
        int cbase = wn_ * 64 + nt * 8 + ecp * 2;
        atomicAdd(&ssum[cbase],     lsum[nt * 2]);
        atomicAdd(&ssq[cbase],      lsq[nt * 2]);
        atomicAdd(&ssum[cbase + 1], lsum[nt * 2 + 1]);
        atomicAdd(&ssq[cbase + 1],  lsq[nt * 2 + 1]);
    }
    __syncthreads();
    if (tid < 128) {
        atomicAdd(&st[so + tid], ssum[tid]);
        atomicAdd(&st[3 * DD + so + tid], ssq[tid]);
    }
}

// ---------------- CSR build ---------------------------------------------------
__global__ void k_hist(const int* __restrict__ dst, int* deg, int e) {
    int i = blockIdx.x * blockDim.x + threadIdx.x;
    if (i < e) atomicAdd(&deg[dst[i]], 1);
}
__global__ void k_scan_block(const int* __restrict__ deg, int* incl, int* bsums, int n) {
    __shared__ int sh[1024];
    int i = blockIdx.x * 1024 + threadIdx.x;
    int v = (i < n) ? deg[i] : 0;
    sh[threadIdx.x] = v;
    __syncthreads();
    for (int off = 1; off < 1024; off <<= 1) {
        int t = (threadIdx.x >= off) ? sh[threadIdx.x - off] : 0;
        __syncthreads();
        sh[threadIdx.x] += t;
        __syncthreads();
    }
    if (i < n) incl[i] = sh[threadIdx.x];
    if (threadIdx.x == 1023) bsums[blockIdx.x] = sh[1023];
}
__global__ void k_scan_sums(int* bsums, int nb) {
    if (threadIdx.x == 0 && blockIdx.x == 0) {
        int run = 0;
        for (int i = 0; i < nb; i++) { int t = bsums[i]; bsums[i] = run; run += t; }
    }
}
__global__ void k_scan_fin(const int* __restrict__ deg, const int* __restrict__ incl,
                           const int* __restrict__ bsums, int* rowptr, int* cursor, int n, int e) {
    int i = blockIdx.x * blockDim.x + threadIdx.x;
    if (i < n) {
        int ex = incl[i] - deg[i] + bsums[i >> 10];
        rowptr[i] = ex;
        cursor[i] = ex;
        if (i == n - 1) rowptr[n] = e;
    }
}
__global__ void k_scatter(const int* __restrict__ src, const int* __restrict__ dst,
                          int* cursor, int* ssrc, int e) {
    int i = blockIdx.x * blockDim.x + threadIdx.x;
    if (i < e) {
        int p = atomicAdd(&cursor[dst[i]], 1);
        ssrc[p] = src[i];
    }
}

// ---------------- graph aggregation: planes in -> planes out, warp per node ----
__global__ void k_agg(const __half* __restrict__ hH, const __half* __restrict__ hL,
                      const int* __restrict__ rowptr, const int* __restrict__ ssrc,
                      __half* mhi, __half* mlo, __half* xhi, __half* xlo, int n) {
    int warp = (blockIdx.x * blockDim.x + threadIdx.x) >> 5;
    int lane = threadIdx.x & 31;
    if (warp >= n) return;
    int beg = rowptr[warp], end = rowptr[warp + 1];
    float4 s  = make_float4(0.f, 0.f, 0.f, 0.f);
    float4 mx = make_float4(-CUDART_INF_F, -CUDART_INF_F, -CUDART_INF_F, -CUDART_INF_F);
    for (int i = beg; i < end; i++) {
        int src = ssrc[i];
        uint2 hi = ((const uint2*)(hH + (size_t)src * DD))[lane];
        uint2 lo = ((const uint2*)(hL + (size_t)src * DD))[lane];
        float4 v = join4(hi, lo);
        s.x += v.x; s.y += v.y; s.z += v.z; s.w += v.w;
        mx.x = fmaxf(mx.x, v.x); mx.y = fmaxf(mx.y, v.y);
        mx.z = fmaxf(mx.z, v.z); mx.w = fmaxf(mx.w, v.w);
    }
    int deg = end - beg;
    float inv = 1.0f / (float)max(deg, 1);
    float4 mo = make_float4(s.x * inv, s.y * inv, s.z * inv, s.w * inv);
    float4 xo = (deg > 0) ? mx : make_float4(0.f, 0.f, 0.f, 0.f);
    uint2 hi, lo;
    split4(mo, hi, lo);
    ((uint2*)(mhi + (size_t)warp * DD))[lane] = hi;
    ((uint2*)(mlo + (size_t)warp * DD))[lane] = lo;
    split4(xo, hi, lo);
    ((uint2*)(xhi + (size_t)warp * DD))[lane] = hi;
    ((uint2*)(xlo + (size_t)warp * DD))[lane] = lo;
}

// ---------------- combine: normalize+relu+ksum -> hi/lo planes ------------------
__device__ __forceinline__ float4 mix3(const float* y, const float* stats,
                                       const float* wrow, const float* gg,
                                       const float* be, int i4, int d0, float fn,
                                       size_t plane_elts) {
    float4 acc = make_float4(0.f, 0.f, 0.f, 0.f);
    #pragma unroll
    for (int k = 0; k < 3; k++) {
        float wk = wrow[k];
        float4 v = ((const float4*)(y + (size_t)k * plane_elts))[i4];
        #pragma unroll
        for (int j = 0; j < 4; j++) {
            int d = d0 + j;
            float mu  = stats[k * DD + d] / fn;
            float var = stats[3 * DD + k * DD + d] / fn - mu * mu;
            float rs  = rsqrtf(var + EPSLN);
            float vv = (&v.x)[j];
            float t = (vv - mu) * rs * gg[k * DD + d] + be[k * DD + d];
            (&acc.x)[j] += wk * fmaxf(t, 0.f);
        }
    }
    return acc;
}

__global__ void k_combine1(const float* __restrict__ y, const float* __restrict__ stats,
                           const float* __restrict__ wrow, const float* __restrict__ gg,
                           const float* __restrict__ be,
                           __half* hiP, __half* loP, int n) {
    int i4 = blockIdx.x * blockDim.x + threadIdx.x;
    int total4 = (n * DD) >> 2;
    if (i4 >= total4) return;
    int d0 = (i4 << 2) & (DD - 1);
    float4 acc = mix3(y, stats, wrow, gg, be, i4, d0, (float)n, (size_t)n * DD);
    uint2 hi, lo;
    split4(acc, hi, lo);
    ((uint2*)hiP)[i4] = hi;
    ((uint2*)loP)[i4] = lo;
}

__global__ void k_combine2(const float* __restrict__ yA, const float* __restrict__ stA,
                           const float* __restrict__ wA, const float* __restrict__ gA,
                           const float* __restrict__ beA,
                           const float* __restrict__ yB, const float* __restrict__ stB,
                           const float* __restrict__ wB, const float* __restrict__ gB,
                           const float* __restrict__ beB,
                           __half* hiP, __half* loP, int n) {
    int i4 = blockIdx.x * blockDim.x + threadIdx.x;
    int total4 = (n * DD) >> 2;
    if (i4 >= total4) return;
    int d0 = (i4 << 2) & (DD - 1);
    float fn = (float)n;
    size_t pe = (size_t)n * DD;
    float4 a = mix3(yA, stA, wA, gA, beA, i4, d0, fn, pe);
    float4 b = mix3(yB, stB, wB, gB, beB, i4, d0, fn, pe);
    float4 acc = make_float4(a.x + b.x, a.y + b.y, a.z + b.z, a.w + b.w);
    uint2 hi, lo;
    split4(acc, hi, lo);
    ((uint2*)hiP)[i4] = hi;
    ((uint2*)loP)[i4] = lo;
}

// ---------------- final column-norm + relu ------------------------------------
__global__ void k_finalnorm(const float* __restrict__ h, const float* __restrict__ stats,
                            const float* __restrict__ gc, const float* __restrict__ bec,
                            float* __restrict__ out, int n) {
    int idx = blockIdx.x * blockDim.x + threadIdx.x;
    int total = n * DD;
    if (idx >= total) return;
    int d = idx & (DD - 1);
    float fn = (float)n;
    float mu  = stats[d] / fn;
    float var = stats[3 * DD + d] / fn - mu * mu;
    float rs  = rsqrtf(var + EPSLN);
    float v = (h[idx] - mu) * rs * gc[d] + bec[d];
    out[idx] = fmaxf(v, 0.f);
}

// ---------------- host orchestration ------------------------------------------
extern "C" void kernel_launch(void* const* d_in, const int* in_sizes, int n_in,
                              void* d_out, int out_size) {
    const float* src_emb = (const float*)d_in[0];
    const float* hr      = (const float*)d_in[1];
    const int*   esrc    = (const int*)d_in[2];
    const int*   edst    = (const int*)d_in[3];
    const float* w_zero  = (const float*)d_in[4];
    const float* w_first = (const float*)d_in[5];
    const float* w_mid   = (const float*)d_in[6];
    const float* w_last  = (const float*)d_in[7];
    const float* W_zero  = (const float*)d_in[8];
    const float* b_zero  = (const float*)d_in[9];
    const float* g_zeroP = (const float*)d_in[10];
    const float* be_zero = (const float*)d_in[11];
    const float* W_first = (const float*)d_in[12];
    const float* b_first = (const float*)d_in[13];
    const float* g_firstP= (const float*)d_in[14];
    const float* be_first= (const float*)d_in[15];
    const float* W_mid   = (const float*)d_in[16];
    const float* b_mid   = (const float*)d_in[17];
    const float* g_midP  = (const float*)d_in[18];
    const float* be_mid  = (const float*)d_in[19];
    const float* W_last  = (const float*)d_in[20];
    const float* b_last  = (const float*)d_in[21];
    const float* g_lastP = (const float*)d_in[22];
    const float* be_last = (const float*)d_in[23];
    const float* W_cat   = (const float*)d_in[24];
    const float* b_cat   = (const float*)d_in[25];
    const float* g_cat   = (const float*)d_in[26];
    const float* be_cat  = (const float*)d_in[27];

    int n = in_sizes[0] / DD;
    int e = in_sizes[2];

    float *yb, *statsA;
    int *deg, *rowptr, *cursor, *ssrc, *bsums;
    __half *wpre, *hlhi, *hllo;
    cudaGetSymbolAddress((void**)&yb, g_y);
    cudaGetSymbolAddress((void**)&statsA, g_statsA);
    cudaGetSymbolAddress((void**)&deg, g_deg);
    cudaGetSymbolAddress((void**)&rowptr, g_rowptr);
    cudaGetSymbolAddress((void**)&cursor, g_cursor);
    cudaGetSymbolAddress((void**)&ssrc, g_ssrc);
    cudaGetSymbolAddress((void**)&bsums, g_bsums);
    cudaGetSymbolAddress((void**)&wpre, g_wpre);
    cudaGetSymbolAddress((void**)&hlhi, g_hlhi);
    cudaGetSymbolAddress((void**)&hllo, g_hllo);

    cudaFuncSetAttribute(k_gemm_mma, cudaFuncAttributeMaxDynamicSharedMemorySize, SMEM_MMA);

    auto HI = [&](int s) { return hlhi + (size_t)s * PLANE; };
    auto LO = [&](int s) { return hllo + (size_t)s * PLANE; };
    auto ST = [&](int s) { return statsA + (size_t)s * 768; };

    int total = n * DD;
    size_t ystride = (size_t)n * DD;
    int gtiles = (n + 127) / 128;
    int ew_grid = (total + 255) / 256;
    int ew_grid4 = (total / 4 + 255) / 256;
    int agg_grid = (n + 7) / 8;
    int eb = (e + 255) / 256;
    int nb1024 = (n + 1023) / 1024;

    // ---- weight prep (stats slots zeroed in first launch) ----
    k_wprep<<<3 * 8, 256>>>(W_zero,  wpre + 0L  * 16384, statsA, 9 * 768);
    k_wprep<<<9 * 8, 256>>>(W_first, wpre + 3L  * 16384, nullptr, 0);
    k_wprep<<<6 * 8, 256>>>(W_mid,   wpre + 12L * 16384, nullptr, 0);
    k_wprep<<<6 * 8, 256>>>(W_last,  wpre + 18L * 16384, nullptr, 0);
    k_wprep<<<3 * 8, 256>>>(W_cat,   wpre + 24L * 16384, nullptr, 0);

    // one-op GEMM launch helper (op candidates = c0,c1,c2 plane slots)
    auto gemm1 = [&](int c0, int c1, int c2, int opmat, const float* B, int stslot) {
        k_gemm_mma<<<dim3(gtiles, 1, 3), 256, SMEM_MMA>>>(
            HI(c0), LO(c0), HI(c1), LO(c1), HI(c2), LO(c2),
            nullptr, nullptr, nullptr, nullptr, nullptr, nullptr,
            wpre + (size_t)opmat * 16384, B, yb, ST(stslot), n, ystride, 0);
    };
    // two-op batched GEMM (opmat, opmat+1 contiguous; bias contiguous; stats slots stslot, stslot+1)
    auto gemm2 = [&](int a0, int a1, int a2, int b0, int b1, int b2,
                     int opmat, const float* B, int stslot) {
        k_gemm_mma<<<dim3(gtiles, 1, 6), 256, SMEM_MMA>>>(
            HI(a0), LO(a0), HI(a1), LO(a1), HI(a2), LO(a2),
            HI(b0), LO(b0), HI(b1), LO(b1), HI(b2), LO(b2),
            wpre + (size_t)opmat * 16384, B, yb, ST(stslot), n, ystride, 0);
    };

    // ---- zero op: pre candidates into slots 0,1,2; hin -> slot 3 ----
    k_pre_hl<<<ew_grid4, 256>>>(src_emb, hr, HI(0), LO(0), HI(1), LO(1), HI(2), LO(2), total / 4);
    gemm1(0, 1, 2, 0, b_zero, 0);

    // ---- CSR build (overlaps nothing, but sits between GEMM and combine) ----
    cudaMemsetAsync(deg, 0, (size_t)n * sizeof(int));
    k_hist<<<eb, 256>>>(edst, deg, e);
    k_scan_block<<<nb1024, 1024>>>(deg, cursor, bsums, n);
    k_scan_sums<<<1, 32>>>(bsums, nb1024);
    k_scan_fin<<<(n + 255) / 256, 256>>>(deg, cursor, bsums, rowptr, cursor, n, e);
    k_scatter<<<eb, 256>>>(esrc, edst, cursor, ssrc, e);

    k_combine1<<<ew_grid4, 256>>>(yb, ST(0), w_zero, g_zeroP, be_zero, HI(3), LO(3), n);

    // ---- first ops ----
    k_agg<<<agg_grid, 256>>>(HI(3), LO(3), rowptr, ssrc, HI(1), LO(1), HI(2), LO(2), n);
    gemm2(3, 1, 2, 3, 1, 2, 3, b_first, 1);                 // first0 -> y0-2/st1, first1 -> y3-5/st2
    k_combine1<<<ew_grid4, 256>>>(yb, ST(1), w_first + 0, g_firstP + 0 * 3 * DD,
                                  be_first + 0 * 3 * DD, HI(4), LO(4), n);   // s0
    k_agg<<<agg_grid, 256>>>(HI(4), LO(4), rowptr, ssrc, HI(1), LO(1), HI(2), LO(2), n);
    gemm1(4, 1, 2, 9, b_first + 6 * DD, 3);                  // first2 -> y0-2/st3
    k_combine2<<<ew_grid4, 256>>>(
        yb + 3 * ystride, ST(2), w_first + 3, g_firstP + 1 * 3 * DD, be_first + 1 * 3 * DD,
        yb, ST(3), w_first + 6, g_firstP + 2 * 3 * DD, be_first + 2 * 3 * DD,
        HI(5), LO(5), n);                                    // s1

    // ---- middle ops ---- (agg(s0) still in slots 1,2)
    gemm1(4, 1, 2, 12, b_mid, 4);                            // mid0 -> y0-2/st4
    k_combine1<<<ew_grid4, 256>>>(yb, ST(4), w_mid + 0, g_midP + 0 * 3 * DD,
                                  be_mid + 0 * 3 * DD, HI(6), LO(6), n);     // m0
    k_agg<<<agg_grid, 256>>>(HI(5), LO(5), rowptr, ssrc, HI(1), LO(1), HI(2), LO(2), n);
    gemm1(5, 1, 2, 15, b_mid + 3 * DD, 5);                   // mid1 -> y0-2/st5
    k_combine1<<<ew_grid4, 256>>>(yb, ST(5), w_mid + 3, g_midP + 1 * 3 * DD,
                                  be_mid + 1 * 3 * DD, HI(7), LO(7), n);     // m1

    // ---- last ops ----
    k_agg<<<agg_grid, 256>>>(HI(6), LO(6), rowptr, ssrc, HI(1), LO(1), HI(2), LO(2), n);
    k_agg<<<agg_grid, 256>>>(HI(7), LO(7), rowptr, ssrc, HI(0), LO(0), HI(3), LO(3), n);
    gemm2(6, 1, 2, 7, 0, 3, 18, b_last, 6);                  // last0 -> y0-2/st6, last1 -> y3-5/st7
    k_combine2<<<ew_grid4, 256>>>(
        yb, ST(6), w_last + 0, g_lastP + 0 * 3 * DD, be_last + 0 * 3 * DD,
        yb + 3 * ystride, ST(7), w_last + 3, g_lastP + 1 * 3 * DD, be_last + 1 * 3 * DD,
        HI(8), LO(8), n);                                    // sl

    // ---- final: cat GEMM (3 K-chunks over m0,m1,sl planes) + column-norm ----
    k_gemm_mma<<<dim3(gtiles, 1, 1), 256, SMEM_MMA>>>(
        HI(6), LO(6), HI(7), LO(7), HI(8), LO(8),
        nullptr, nullptr, nullptr, nullptr, nullptr, nullptr,
        wpre + 24L * 16384, b_cat, yb, ST(8), n, ystride, 1);
    k_finalnorm<<<ew_grid, 256>>>(yb, ST(8), g_cat, be_cat, (float*)d_out, n);
}